// round 16
// baseline (speedup 1.0000x reference)
#include <cuda_runtime.h>
#include <math.h>

// Brunel network forward, GB300 — round 13.
// Round 11 + atomics-free prep: warp counting-sort via __match_any_sync into
// class-strided scratch (no histogram atomics, no prefix pass). The shared-
// atomic prep_sort (~150us/replay) was the hidden bottleneck. Window kernel
// unchanged. Counts identical -> numerics bit-identical.

#define NN 10000
#define CC 1000
#define CE 800
#define BB 8
#define TT 200
#define WS 8
#define NWIN 25
#define REFS 20
#define TAB_I 201
#define THREADS 288          // 9 warps x 4 neurons = 36 >= CHUNK
#define CHUNK 34
#define GRID 295             // 295*34 = 10030 >= NN
#define SENT 10000           // sentinel base: 10000+c has bank class c
#define SMEM_BYTES ((NN + 16) * 8)
#define CAP_E 128
#define CAP_I 48

typedef unsigned long long u64;
typedef unsigned int u32;
typedef unsigned short u16;

__device__ u16   g_excp[NN * 832];            // [n][r 0..12][gl 0..7][k 0..7]
__device__ u16   g_inhp[NN * 256];            // [n][r 0..3][gl][k]
__device__ u16   g_scr_e[NN * 16 * CAP_E];    // class-strided exc scratch
__device__ u16   g_scr_i[NN * 16 * CAP_I];
__device__ int   g_cnt[NN][32];               // [0:16) exc class counts, [16:32) inh
__device__ float g_v[BB * NN];
__device__ int   g_ref[BB * NN];
__device__ u64   g_spk[3][NN];                // byte q bit s = spike(batch rev3(q), step s)
__device__ float g_tab2[801 * TAB_I];

// ---- prep 1: atomics-free class sort (warp per neuron) ----
__global__ void prep_sort(const int* __restrict__ idx) {
    __shared__ int s_base[8][32];
    const int w = threadIdx.x >> 5, lane = threadIdx.x & 31;
    const int n = blockIdx.x * 8 + w;          // grid 1250 -> exactly NN
    const int* row = idx + n * CC;
    const u32 full = 0xFFFFFFFFu;
    const u32 below = (1u << lane) - 1u;

    s_base[w][lane] = 0;
    __syncwarp();

    // exc: 800 = 25*32
    for (int it = 0; it < 25; it++) {
        int v = row[it * 32 + lane];
        int c = v & 15;
        u32 mm = __match_any_sync(full, c);
        int rank = __popc(mm & below);
        int b = s_base[w][c];
        int slot = b + rank;
        if (slot < CAP_E) g_scr_e[(n * 16 + c) * CAP_E + slot] = (u16)v;
        __syncwarp();
        if ((mm & (0u - mm)) == (1u << lane))      // leader = lowest lane
            s_base[w][c] = b + __popc(mm);
        __syncwarp();
    }
    // inh: 192 = 6*32
    for (int it = 0; it < 6; it++) {
        int v = row[CE + it * 32 + lane];
        int c = v & 15;
        u32 mm = __match_any_sync(full, c);
        int rank = __popc(mm & below);
        int b = s_base[w][16 + c];
        int slot = b + rank;
        if (slot < CAP_I) g_scr_i[(n * 16 + c) * CAP_I + slot] = (u16)v;
        __syncwarp();
        if ((mm & (0u - mm)) == (1u << lane))
            s_base[w][16 + c] = b + __popc(mm);
        __syncwarp();
    }
    // inh tail: 8 items (lanes 0..7)
    if (lane < 8) {
        int v = row[992 + lane];
        int c = v & 15;
        u32 mm = __match_any_sync(0xFFu, c);
        int rank = __popc(mm & below);
        int b = s_base[w][16 + c];
        int slot = b + rank;
        if (slot < CAP_I) g_scr_i[(n * 16 + c) * CAP_I + slot] = (u16)v;
        __syncwarp(0xFFu);
        if ((mm & (0u - mm)) == (1u << lane))
            s_base[w][16 + c] = b + __popc(mm);
    }
    __syncwarp();
    g_cnt[n][lane] = s_base[w][lane];
}

// ---- prep 2: deal into bank-balanced layout + overflow fixup ----
__global__ void prep_deal() {
    __shared__ u16 s_ov[8][128];
    __shared__ u16 s_sv[8][128];
    const int w = threadIdx.x >> 5, lane = threadIdx.x & 31;
    const int n = blockIdx.x * 8 + w;
    const int P = n & 1;                      // warp-slot parity
    const u32 full = 0xFFFFFFFFu;

    // ===== exc: 832 slots, cells 104, per-class cell cap 52 =====
    {
        int nsent = 0;
        for (int it = 0; it < 26; it++) {
            int u = it * 32 + lane;            // slot id
            int m = u >> 3, s = u & 7;         // cell, class-slot
            int par = (m ^ P) & 1;
            int c = 2 * s + par;
            int j = m >> 1;
            int ncl = g_cnt[n][c];
            bool sent = (j >= ncl);
            u16 val = sent ? (u16)(SENT + c) : g_scr_e[(n * 16 + c) * CAP_E + j];
            int r = m >> 3, k = m & 7;
            g_excp[n * 832 + (r * 8 + s) * 8 + k] = val;
            u32 bal = __ballot_sync(full, sent);
            if (sent) {
                int rank = __popc(bal & ((1u << lane) - 1u));
                int pos = nsent + rank;
                if (pos < 128) s_sv[w][pos] = (u16)u;
            }
            nsent += __popc(bal);
        }
        // collect overflow (class items with j >= 52)
        int ovc = 0;
        if (lane < 16) {
            int ncl = g_cnt[n][lane];
            ovc = ncl > 52 ? ncl - 52 : 0;
        }
        int x = ovc;
        for (int d = 1; d < 16; d <<= 1) {
            int y = __shfl_up_sync(full, x, d);
            if (lane >= d) x += y;
        }
        int excl = x - ovc;
        int totOv = __shfl_sync(full, x, 15);
        if (lane < 16)
            for (int i = 0; i < ovc; i++)
                if (excl + i < 128)
                    s_ov[w][excl + i] = g_scr_e[(n * 16 + lane) * CAP_E + 52 + i];
        __syncwarp();
        for (int i = lane; i < totOv && i < 128 && i < nsent; i += 32) {
            int u = s_sv[w][i];
            int m = u >> 3, s = u & 7, r = m >> 3, k = m & 7;
            g_excp[n * 832 + (r * 8 + s) * 8 + k] = s_ov[w][i];
        }
        __syncwarp();
    }
    // ===== inh: 256 slots, cells 32, cap 16 =====
    {
        int nsent = 0;
        for (int it = 0; it < 8; it++) {
            int u = it * 32 + lane;
            int m = u >> 3, s = u & 7;
            int par = (m ^ P) & 1;
            int c = 2 * s + par;
            int j = m >> 1;
            int ncl = g_cnt[n][16 + c];
            bool sent = (j >= ncl);
            u16 val = sent ? (u16)(SENT + c) : g_scr_i[(n * 16 + c) * CAP_I + j];
            int r = m >> 3, k = m & 7;
            g_inhp[n * 256 + (r * 8 + s) * 8 + k] = val;
            u32 bal = __ballot_sync(full, sent);
            if (sent) {
                int rank = __popc(bal & ((1u << lane) - 1u));
                int pos = nsent + rank;
                if (pos < 128) s_sv[w][pos] = (u16)u;
            }
            nsent += __popc(bal);
        }
        int ovc = 0;
        if (lane < 16) {
            int ncl = g_cnt[n][16 + lane];
            ovc = ncl > 16 ? ncl - 16 : 0;
        }
        int x = ovc;
        for (int d = 1; d < 16; d <<= 1) {
            int y = __shfl_up_sync(full, x, d);
            if (lane >= d) x += y;
        }
        int excl = x - ovc;
        int totOv = __shfl_sync(full, x, 15);
        if (lane < 16)
            for (int i = 0; i < ovc; i++)
                if (excl + i < 128)
                    s_ov[w][excl + i] = g_scr_i[(n * 16 + lane) * CAP_I + 16 + i];
        __syncwarp();
        for (int i = lane; i < totOv && i < 128 && i < nsent; i += 32) {
            int u = s_sv[w][i];
            int m = u >> 3, s = u & 7, r = m >> 3, k = m & 7;
            g_inhp[n * 256 + (r * 8 + s) * 8 + k] = s_ov[w][i];
        }
    }
}

__global__ void init_kernel(const float* __restrict__ w) {
    int i = blockIdx.x * blockDim.x + threadIdx.x;
    int stride = gridDim.x * blockDim.x;
    for (int k = i; k < BB * NN; k += stride) { g_v[k] = 0.0f; g_ref[k] = 0; }
    u64* sp = &g_spk[0][0];
    for (int k = i; k < 3 * NN; k += stride) sp[k] = 0ull;
    if (i < 801) {   // exact sequential sums: i adds of w[0], then j adds of w[CE]
        float we = w[0];
        float wi = w[CE];
        float a = 0.0f;
        for (int k = 0; k < i; k++) a = __fadd_rn(a, we);
        g_tab2[i * TAB_I] = a;
        for (int j = 1; j < TAB_I; j++) {
            a = __fadd_rn(a, wi);
            g_tab2[i * TAB_I + j] = a;
        }
    }
}

__device__ __forceinline__ u64 csa64(u64& acc, u64 a, u64 b) {
    u64 u = acc ^ a;
    u64 carry = (acc & a) | (u & b);
    acc = u ^ b;
    return carry;
}

#define EROUND7(P1,P2,P4,P8,P16,P32,P64, q) do {                               \
    u64 m0 = s_mask[(q).x & 0xFFFFu], m1 = s_mask[(q).x >> 16];                \
    u64 m2 = s_mask[(q).y & 0xFFFFu], m3 = s_mask[(q).y >> 16];                \
    u64 m4 = s_mask[(q).z & 0xFFFFu], m5 = s_mask[(q).z >> 16];                \
    u64 m6 = s_mask[(q).w & 0xFFFFu], m7 = s_mask[(q).w >> 16];                \
    u64 c1 = csa64(P1, m0, m1);                                                \
    u64 c2 = csa64(P1, m2, m3);                                                \
    u64 dA = csa64(P2, c1, c2);                                                \
    u64 c3 = csa64(P1, m4, m5);                                                \
    u64 c4 = csa64(P1, m6, m7);                                                \
    u64 dB = csa64(P2, c3, c4);                                                \
    u64 cc = csa64(P4, dA, dB);                                                \
    u64 t  = P8  & cc; P8  ^= cc;                                              \
    u64 t2 = P16 & t;  P16 ^= t;                                               \
    u64 t3 = P32 & t2; P32 ^= t2;                                              \
    P64 ^= t3;                                                                 \
} while (0)

#define EROUND5(P1,P2,P4,P8,P16, q) do {                                       \
    u64 m0 = s_mask[(q).x & 0xFFFFu], m1 = s_mask[(q).x >> 16];                \
    u64 m2 = s_mask[(q).y & 0xFFFFu], m3 = s_mask[(q).y >> 16];                \
    u64 m4 = s_mask[(q).z & 0xFFFFu], m5 = s_mask[(q).z >> 16];                \
    u64 m6 = s_mask[(q).w & 0xFFFFu], m7 = s_mask[(q).w >> 16];                \
    u64 c1 = csa64(P1, m0, m1);                                                \
    u64 c2 = csa64(P1, m2, m3);                                                \
    u64 dA = csa64(P2, c1, c2);                                                \
    u64 c3 = csa64(P1, m4, m5);                                                \
    u64 c4 = csa64(P1, m6, m7);                                                \
    u64 dB = csa64(P2, c3, c4);                                                \
    u64 cc = csa64(P4, dA, dB);                                                \
    u64 t  = P8 & cc; P8 ^= cc;                                                \
    P16 ^= t;                                                                  \
} while (0)

// 3-level width-halving butterfly within each 8-lane group.
template<int P0>
__device__ __forceinline__ void bfly3(const u64* q, u32* p, int lane) {
    const u32 full = 0xFFFFFFFFu;
    {   // level 0: u64 -> u32, partner lane^1
        bool hk = (lane & 1);
        u32 c = 0;
        #pragma unroll
        for (int k = 0; k < P0; k++) {
            u32 lo = (u32)q[k], hi = (u32)(q[k] >> 32);
            u32 give = hk ? lo : hi;
            u32 own  = hk ? hi : lo;
            u32 r = __shfl_xor_sync(full, give, 1);
            u32 x = own ^ r;
            if (k == 0) { p[0] = x; c = own & r; }
            else        { p[k] = x ^ c; c = (own & r) | (x & c); }
        }
        p[P0] = c;
    }
    #pragma unroll
    for (int lev = 1; lev <= 2; lev++) {   // widths 16, 8
        const int W = (lev == 1) ? 16 : 8;
        const int P = P0 + lev;
        u32 sh = ((lane >> lev) & 1) ? (u32)W : 0u;
        u32 c = 0;
        #pragma unroll
        for (int k = 0; k < P0 + 3; k++) {
            if (k < P) {
                u32 r = __shfl_xor_sync(full, p[k], 1 << lev);
                u32 own = p[k] >> sh;
                u32 rec = r >> sh;
                u32 x = own ^ rec;
                if (k == 0) { p[0] = x; c = own & rec; }
                else        { p[k] = x ^ c; c = (own & rec) | (x & c); }
            }
        }
        p[P] = c;
    }
}

__global__ void __launch_bounds__(THREADS, 2) win_kernel(
    const float* __restrict__ ext,
    float* __restrict__ out_spk,
    float* __restrict__ out_v,
    int t0, int kwin, float decay)
{
    extern __shared__ u64 s_mask[];   // NN + 16 sentinel entries

    const int tid  = threadIdx.x;
    const int lane = tid & 31;
    const int warp = tid >> 5;

    if (kwin > 0) {
        const u64* A = g_spk[(kwin + 1) % 3];   // window k-2
        const u64* B = g_spk[(kwin + 2) % 3];   // window k-1
        for (int i = tid; i < NN; i += THREADS) {
            u64 a = A[i], b = B[i];
            s_mask[i] = ((a >> 1) & 0x7F7F7F7F7F7F7F7Full)
                      | ((b & 0x0101010101010101ull) << 7);
        }
        if (tid < 16) s_mask[NN + tid] = 0ull;   // class-matched sentinels
        __syncthreads();
    }

    const int g   = lane >> 3;          // neuron within warp (0..3)
    const int gl  = lane & 7;           // group lane = batch
    const int ln  = warp * 4 + g;       // local neuron in block
    const int n   = blockIdx.x * CHUNK + ln;
    const bool act = (ln < CHUNK) && (n < NN);
    const int nc  = act ? n : 0;        // clamped for safe loads

    int ce_[WS], ci_[WS];

    if (kwin > 0) {
        u64 e[7], f[5];
        {
            u64 e1=0,e2=0,e4=0,e8=0,e16=0,e32=0,e64=0;
            const uint4* ep = (const uint4*)(g_excp + (size_t)nc * 832) + gl;
            #pragma unroll
            for (int r = 0; r < 13; r++) {
                uint4 q = ep[r * 8];
                EROUND7(e1,e2,e4,e8,e16,e32,e64, q);
            }
            e[0]=e1; e[1]=e2; e[2]=e4; e[3]=e8; e[4]=e16; e[5]=e32; e[6]=e64;
        }
        {
            u64 f1=0,f2=0,f4=0,f8=0,f16=0;
            const uint4* ip = (const uint4*)(g_inhp + (size_t)nc * 256) + gl;
            #pragma unroll
            for (int r = 0; r < 4; r++) {
                uint4 q = ip[r * 8];
                EROUND5(f1,f2,f4,f8,f16, q);
            }
            f[0]=f1; f[1]=f2; f[2]=f4; f[3]=f8; f[4]=f16;
        }

        u32 pe[10], pf[8];
        bfly3<7>(e, pe, lane);   // counts <= 832 < 1024
        bfly3<5>(f, pf, lane);   // counts <= 256

        #pragma unroll
        for (int s = 0; s < WS; s++) {
            u32 a = 0, b2 = 0;
            #pragma unroll
            for (int k = 0; k < 10; k++) a |= ((pe[k] >> s) & 1u) << k;
            #pragma unroll
            for (int k = 0; k < 8; k++)  b2 |= ((pf[k] >> s) & 1u) << k;
            ce_[s] = (int)a; ci_[s] = (int)b2;
        }
    } else {
        #pragma unroll
        for (int s = 0; s < WS; s++) { ce_[s] = 0; ci_[s] = 0; }
    }

    // ---- LIF epilogue: all 32 lanes active (4 neurons x 8 batches) ----
    const int b = gl;
    float v = 0.0f; int rf = 0;
    float acc[WS], ex[WS];
    if (act) {
        const int sid = b * NN + n;
        v  = g_v[sid];
        rf = g_ref[sid];
        #pragma unroll
        for (int s = 0; s < WS; s++)
            acc[s] = g_tab2[ce_[s] * TAB_I + ci_[s]];
        #pragma unroll
        for (int s = 0; s < WS; s++)
            ex[s] = ext[((size_t)(t0 + s) * BB + b) * NN + n];
    }

    u32 mybits = 0;
    #pragma unroll
    for (int s = 0; s < WS; s++) {
        if (act) {
            float vn = __fadd_rn(__fadd_rn(__fmul_rn(v, decay), acc[s]), ex[s]);
            if (rf > 0) vn = 10.0f;
            bool sp = (vn >= 20.0f);
            float vo = sp ? 10.0f : vn;
            int rm = rf - 1; if (rm < 0) rm = 0;
            rf = sp ? REFS : rm;
            v = vo;
            mybits |= (sp ? 1u : 0u) << s;
            size_t o = ((size_t)(t0 + s) * BB + b) * NN + n;
            out_spk[o] = sp ? 1.0f : 0.0f;
            out_v[o]   = vo;
        }
    }
    if (act) {
        const int sid = b * NN + n;
        g_v[sid] = v; g_ref[sid] = rf;
        const int q = ((gl & 1) << 2) | (gl & 2) | ((gl >> 2) & 1);
        ((unsigned char*)&g_spk[kwin % 3][n])[q] = (unsigned char)mybits;
    }
}

extern "C" void kernel_launch(void* const* d_in, const int* in_sizes, int n_in,
                              void* d_out, int out_size)
{
    const float* ext = (const float*)d_in[0];
    const float* w   = (const float*)d_in[1];
    const int*   idx = (const int*)d_in[2];

    float* out     = (float*)d_out;
    float* out_spk = out;
    float* out_v   = out + (size_t)TT * BB * NN;

    float decay = (float)exp(-0.005);

    cudaFuncSetAttribute(win_kernel, cudaFuncAttributeMaxDynamicSharedMemorySize,
                         SMEM_BYTES);

    prep_sort<<<NN / 8, 256>>>(idx);
    prep_deal<<<NN / 8, 256>>>();
    init_kernel<<<160, 256>>>(w);

    for (int k = 0; k < NWIN; k++) {
        win_kernel<<<GRID, THREADS, SMEM_BYTES>>>(ext, out_spk, out_v,
                                                  k * WS, k, decay);
    }
}

// round 17
// speedup vs baseline: 1.2297x; 1.2297x over previous
#include <cuda_runtime.h>
#include <math.h>

// Brunel network forward, GB300 — round 17.
// Two graph nodes total:
//  1) prep_all: init + per-neuron class sort + bank-conflict-free deal, all in
//     shared-memory scratch (one launch).
//  2) sim_all: persistent kernel running all 25 windows with a software
//     grid-wide barrier between windows (296 CTAs, provably all resident).
// LIF state (v, ref) lives in registers for the whole simulation.
// Counts/table numerics identical to round 12 -> rel_err pinned at 6.5e-8.

#define NN 10000
#define CC 1000
#define CE 800
#define BB 8
#define TT 200
#define WS 8
#define NWIN 25
#define REFS 20
#define TAB_I 201
#define THREADS 288
#define CHUNK 34
#define NBLKS 296            // 2 per SM x 148 SMs -> all resident (wave 1)
#define SENT 10000           // sentinel base: 10000+c has bank class c
#define SMEM_BYTES ((NN + 16) * 8)

typedef unsigned long long u64;
typedef unsigned int u32;
typedef unsigned short u16;

__device__ u16   g_excp[NN * 832];   // [n][r 0..12][gl 0..7][k 0..7]
__device__ u16   g_inhp[NN * 256];   // [n][r 0..3][gl][k]
__device__ u64   g_spk[3][NN];       // byte q bit s = spike(batch rev3(q), step s)
__device__ float g_tab2[801 * TAB_I];
__device__ u32   g_bar_cnt;
__device__ u32   g_bar_gen;

// ================= prep: init + sort + deal (one kernel) =================
__global__ void __launch_bounds__(256) prep_all(const int* __restrict__ idx,
                                                const float* __restrict__ w) {
    __shared__ u16 s_srt_e[8][800];
    __shared__ u16 s_srt_i[8][208];
    __shared__ int s_cnt[8][32];
    __shared__ int s_cur[8][32];
    __shared__ u16 s_ov[8][128];
    __shared__ u16 s_sv[8][128];

    const int tid = threadIdx.x, wp = tid >> 5, lane = tid & 31;
    const u32 full = 0xFFFFFFFFu;

    // ---- init (grid-strided across the 1250x256 threads) ----
    int gi = blockIdx.x * 256 + tid;
    if (gi < 3 * NN) (&g_spk[0][0])[gi] = 0ull;
    if (gi == 0) { g_bar_cnt = 0u; g_bar_gen = 0u; }
    if (gi < 801) {   // exact sequential sums: gi adds of w[0], then j adds of w[CE]
        float we = w[0];
        float wi = w[CE];
        float a = 0.0f;
        for (int k = 0; k < gi; k++) a = __fadd_rn(a, we);
        g_tab2[gi * TAB_I] = a;
        for (int j = 1; j < TAB_I; j++) {
            a = __fadd_rn(a, wi);
            g_tab2[gi * TAB_I + j] = a;
        }
    }

    // ---- class sort (warp per neuron; grid 1250 -> exactly NN) ----
    const int n = blockIdx.x * 8 + wp;
    const int* row = idx + n * CC;

    s_cnt[wp][lane] = 0;
    __syncwarp();
    for (int it = 0; it < 25; it++)
        atomicAdd(&s_cnt[wp][row[it * 32 + lane] & 15], 1);
    for (int it = 0; it < 6; it++)
        atomicAdd(&s_cnt[wp][16 + (row[CE + it * 32 + lane] & 15)], 1);
    if (lane < 8)
        atomicAdd(&s_cnt[wp][16 + (row[992 + lane] & 15)], 1);
    __syncwarp();
    if (lane == 0) {
        int a = 0;
        for (int c = 0; c < 16; c++) { s_cur[wp][c] = a;      a += s_cnt[wp][c]; }
        a = 0;
        for (int c = 0; c < 16; c++) { s_cur[wp][16 + c] = a; a += s_cnt[wp][16 + c]; }
    }
    __syncwarp();
    for (int it = 0; it < 25; it++) {
        int v = row[it * 32 + lane];
        int p = atomicAdd(&s_cur[wp][v & 15], 1);
        s_srt_e[wp][p] = (u16)v;
    }
    for (int it = 0; it < 6; it++) {
        int v = row[CE + it * 32 + lane];
        int p = atomicAdd(&s_cur[wp][16 + (v & 15)], 1);
        s_srt_i[wp][p] = (u16)v;
    }
    if (lane < 8) {
        int v = row[992 + lane];
        int p = atomicAdd(&s_cur[wp][16 + (v & 15)], 1);
        s_srt_i[wp][p] = (u16)v;
    }
    __syncwarp();
    // after placement: s_cur[c] = start+cnt  ->  start = s_cur[c]-s_cnt[c]

    const int P = n & 1;   // warp-slot parity

    // ===== deal exc: 832 slots, cells 104, per-class cell cap 52 =====
    {
        int nsent = 0;
        for (int it = 0; it < 26; it++) {
            int u = it * 32 + lane;            // slot id
            int m = u >> 3, s8 = u & 7;        // cell, class-slot
            int c = 2 * s8 + ((m ^ P) & 1);
            int j = m >> 1;
            int ncl = s_cnt[wp][c];
            bool sent = (j >= ncl);
            int ofs = s_cur[wp][c] - ncl;
            u16 val = sent ? (u16)(SENT + c) : s_srt_e[wp][ofs + j];
            int r = m >> 3, k = m & 7;
            g_excp[n * 832 + (r * 8 + s8) * 8 + k] = val;
            u32 bal = __ballot_sync(full, sent);
            if (sent) {
                int rank = __popc(bal & ((1u << lane) - 1u));
                int pos = nsent + rank;
                if (pos < 128) s_sv[wp][pos] = (u16)u;
            }
            nsent += __popc(bal);
        }
        int ovc = 0, start = 0;
        if (lane < 16) {
            int ncl = s_cnt[wp][lane];
            ovc = ncl > 52 ? ncl - 52 : 0;
            start = s_cur[wp][lane] - ncl + 52;
        }
        int x = ovc;
        for (int d = 1; d < 16; d <<= 1) {
            int y = __shfl_up_sync(full, x, d);
            if (lane >= d) x += y;
        }
        int excl = x - ovc;
        int totOv = __shfl_sync(full, x, 15);
        if (lane < 16)
            for (int i = 0; i < ovc; i++)
                if (excl + i < 128) s_ov[wp][excl + i] = s_srt_e[wp][start + i];
        __syncwarp();
        for (int i = lane; i < totOv && i < 128 && i < nsent; i += 32) {
            int u = s_sv[wp][i];
            int m = u >> 3, s8 = u & 7, r = m >> 3, k = m & 7;
            g_excp[n * 832 + (r * 8 + s8) * 8 + k] = s_ov[wp][i];
        }
        __syncwarp();
    }
    // ===== deal inh: 256 slots, cells 32, cap 16 =====
    {
        int nsent = 0;
        for (int it = 0; it < 8; it++) {
            int u = it * 32 + lane;
            int m = u >> 3, s8 = u & 7;
            int c = 2 * s8 + ((m ^ P) & 1);
            int j = m >> 1;
            int ncl = s_cnt[wp][16 + c];
            bool sent = (j >= ncl);
            int ofs = s_cur[wp][16 + c] - ncl;
            u16 val = sent ? (u16)(SENT + c) : s_srt_i[wp][ofs + j];
            int r = m >> 3, k = m & 7;
            g_inhp[n * 256 + (r * 8 + s8) * 8 + k] = val;
            u32 bal = __ballot_sync(full, sent);
            if (sent) {
                int rank = __popc(bal & ((1u << lane) - 1u));
                int pos = nsent + rank;
                if (pos < 128) s_sv[wp][pos] = (u16)u;
            }
            nsent += __popc(bal);
        }
        int ovc = 0, start = 0;
        if (lane < 16) {
            int ncl = s_cnt[wp][16 + lane];
            ovc = ncl > 16 ? ncl - 16 : 0;
            start = s_cur[wp][16 + lane] - ncl + 16;
        }
        int x = ovc;
        for (int d = 1; d < 16; d <<= 1) {
            int y = __shfl_up_sync(full, x, d);
            if (lane >= d) x += y;
        }
        int excl = x - ovc;
        int totOv = __shfl_sync(full, x, 15);
        if (lane < 16)
            for (int i = 0; i < ovc; i++)
                if (excl + i < 128) s_ov[wp][excl + i] = s_srt_i[wp][start + i];
        __syncwarp();
        for (int i = lane; i < totOv && i < 128 && i < nsent; i += 32) {
            int u = s_sv[wp][i];
            int m = u >> 3, s8 = u & 7, r = m >> 3, k = m & 7;
            g_inhp[n * 256 + (r * 8 + s8) * 8 + k] = s_ov[wp][i];
        }
    }
}

// ================= sim: persistent, all 25 windows =================
__device__ __forceinline__ u64 csa64(u64& acc, u64 a, u64 b) {
    u64 u = acc ^ a;
    u64 carry = (acc & a) | (u & b);
    acc = u ^ b;
    return carry;
}

#define EROUND7(P1,P2,P4,P8,P16,P32,P64, q) do {                               \
    u64 m0 = s_mask[(q).x & 0xFFFFu], m1 = s_mask[(q).x >> 16];                \
    u64 m2 = s_mask[(q).y & 0xFFFFu], m3 = s_mask[(q).y >> 16];                \
    u64 m4 = s_mask[(q).z & 0xFFFFu], m5 = s_mask[(q).z >> 16];                \
    u64 m6 = s_mask[(q).w & 0xFFFFu], m7 = s_mask[(q).w >> 16];                \
    u64 c1 = csa64(P1, m0, m1);                                                \
    u64 c2 = csa64(P1, m2, m3);                                                \
    u64 dA = csa64(P2, c1, c2);                                                \
    u64 c3 = csa64(P1, m4, m5);                                                \
    u64 c4 = csa64(P1, m6, m7);                                                \
    u64 dB = csa64(P2, c3, c4);                                                \
    u64 cc = csa64(P4, dA, dB);                                                \
    u64 t  = P8  & cc; P8  ^= cc;                                              \
    u64 t2 = P16 & t;  P16 ^= t;                                               \
    u64 t3 = P32 & t2; P32 ^= t2;                                              \
    P64 ^= t3;                                                                 \
} while (0)

#define EROUND5(P1,P2,P4,P8,P16, q) do {                                       \
    u64 m0 = s_mask[(q).x & 0xFFFFu], m1 = s_mask[(q).x >> 16];                \
    u64 m2 = s_mask[(q).y & 0xFFFFu], m3 = s_mask[(q).y >> 16];                \
    u64 m4 = s_mask[(q).z & 0xFFFFu], m5 = s_mask[(q).z >> 16];                \
    u64 m6 = s_mask[(q).w & 0xFFFFu], m7 = s_mask[(q).w >> 16];                \
    u64 c1 = csa64(P1, m0, m1);                                                \
    u64 c2 = csa64(P1, m2, m3);                                                \
    u64 dA = csa64(P2, c1, c2);                                                \
    u64 c3 = csa64(P1, m4, m5);                                                \
    u64 c4 = csa64(P1, m6, m7);                                                \
    u64 dB = csa64(P2, c3, c4);                                                \
    u64 cc = csa64(P4, dA, dB);                                                \
    u64 t  = P8 & cc; P8 ^= cc;                                                \
    P16 ^= t;                                                                  \
} while (0)

template<int P0>
__device__ __forceinline__ void bfly3(const u64* q, u32* p, int lane) {
    const u32 full = 0xFFFFFFFFu;
    {   // level 0: u64 -> u32, partner lane^1
        bool hk = (lane & 1);
        u32 c = 0;
        #pragma unroll
        for (int k = 0; k < P0; k++) {
            u32 lo = (u32)q[k], hi = (u32)(q[k] >> 32);
            u32 give = hk ? lo : hi;
            u32 own  = hk ? hi : lo;
            u32 r = __shfl_xor_sync(full, give, 1);
            u32 x = own ^ r;
            if (k == 0) { p[0] = x; c = own & r; }
            else        { p[k] = x ^ c; c = (own & r) | (x & c); }
        }
        p[P0] = c;
    }
    #pragma unroll
    for (int lev = 1; lev <= 2; lev++) {   // widths 16, 8
        const int W = (lev == 1) ? 16 : 8;
        const int P = P0 + lev;
        u32 sh = ((lane >> lev) & 1) ? (u32)W : 0u;
        u32 c = 0;
        #pragma unroll
        for (int k = 0; k < P0 + 3; k++) {
            if (k < P) {
                u32 r = __shfl_xor_sync(full, p[k], 1 << lev);
                u32 own = p[k] >> sh;
                u32 rec = r >> sh;
                u32 x = own ^ rec;
                if (k == 0) { p[0] = x; c = own & rec; }
                else        { p[k] = x ^ c; c = (own & rec) | (x & c); }
            }
        }
        p[P] = c;
    }
}

__global__ void __launch_bounds__(THREADS, 2) sim_all(
    const float* __restrict__ ext,
    float* __restrict__ out_spk,
    float* __restrict__ out_v,
    float decay)
{
    extern __shared__ u64 s_mask[];   // NN + 16 sentinel entries

    const int tid  = threadIdx.x;
    const int lane = tid & 31;
    const int warp = tid >> 5;
    const u32 full = 0xFFFFFFFFu;

    const int g    = lane >> 3;          // neuron within warp (0..3)
    const int gl   = lane & 7;           // group lane = batch
    const int ln   = warp * 4 + g;       // local neuron in block
    const int nbeg = blockIdx.x * CHUNK;
    const int n    = nbeg + ln;
    const bool act = (ln < CHUNK) && (n < NN);
    const int nc   = act ? n : 0;        // clamped for safe loads
    const int b    = gl;                 // batch
    const int qb   = ((gl & 1) << 2) | (gl & 2) | ((gl >> 2) & 1);  // rev3(gl)

    if (tid < 16) s_mask[NN + tid] = 0ull;   // class-matched sentinels (once)

    // Persistent LIF state in registers for the whole simulation
    float v = 0.0f;
    int   rf = 0;

    for (int kwin = 0; kwin < NWIN; kwin++) {
        const int t0 = kwin * WS;

        if (kwin > 0 && nbeg < NN) {
            const u64* A = g_spk[(kwin + 1) % 3];   // window k-2
            const u64* B = g_spk[(kwin + 2) % 3];   // window k-1
            for (int i = tid; i < NN; i += THREADS) {
                u64 a = A[i], bb = B[i];
                s_mask[i] = ((a >> 1) & 0x7F7F7F7F7F7F7F7Full)
                          | ((bb & 0x0101010101010101ull) << 7);
            }
            __syncthreads();
        }

        int ce_[WS], ci_[WS];

        if (kwin > 0 && nbeg < NN) {
            u64 e[7], f[5];
            {
                u64 e1=0,e2=0,e4=0,e8=0,e16=0,e32=0,e64=0;
                const uint4* ep = (const uint4*)(g_excp + (size_t)nc * 832) + gl;
                #pragma unroll
                for (int r = 0; r < 13; r++) {
                    uint4 q = ep[r * 8];
                    EROUND7(e1,e2,e4,e8,e16,e32,e64, q);
                }
                e[0]=e1; e[1]=e2; e[2]=e4; e[3]=e8; e[4]=e16; e[5]=e32; e[6]=e64;
            }
            {
                u64 f1=0,f2=0,f4=0,f8=0,f16=0;
                const uint4* ip = (const uint4*)(g_inhp + (size_t)nc * 256) + gl;
                #pragma unroll
                for (int r = 0; r < 4; r++) {
                    uint4 q = ip[r * 8];
                    EROUND5(f1,f2,f4,f8,f16, q);
                }
                f[0]=f1; f[1]=f2; f[2]=f4; f[3]=f8; f[4]=f16;
            }

            u32 pe[10], pf[8];
            bfly3<7>(e, pe, lane);   // counts <= 832 < 1024
            bfly3<5>(f, pf, lane);   // counts <= 256

            #pragma unroll
            for (int s = 0; s < WS; s++) {
                u32 a = 0, b2 = 0;
                #pragma unroll
                for (int k = 0; k < 10; k++) a |= ((pe[k] >> s) & 1u) << k;
                #pragma unroll
                for (int k = 0; k < 8; k++)  b2 |= ((pf[k] >> s) & 1u) << k;
                ce_[s] = (int)a; ci_[s] = (int)b2;
            }
        } else {
            #pragma unroll
            for (int s = 0; s < WS; s++) { ce_[s] = 0; ci_[s] = 0; }
        }

        // ---- LIF epilogue (identical numerics) ----
        float acc[WS], ex[WS];
        if (act) {
            #pragma unroll
            for (int s = 0; s < WS; s++)
                acc[s] = g_tab2[ce_[s] * TAB_I + ci_[s]];
            #pragma unroll
            for (int s = 0; s < WS; s++)
                ex[s] = ext[((size_t)(t0 + s) * BB + b) * NN + n];
        }
        u32 mybits = 0;
        #pragma unroll
        for (int s = 0; s < WS; s++) {
            if (act) {
                float vn = __fadd_rn(__fadd_rn(__fmul_rn(v, decay), acc[s]), ex[s]);
                if (rf > 0) vn = 10.0f;
                bool sp = (vn >= 20.0f);
                float vo = sp ? 10.0f : vn;
                int rm = rf - 1; if (rm < 0) rm = 0;
                rf = sp ? REFS : rm;
                v = vo;
                mybits |= (sp ? 1u : 0u) << s;
                size_t o = ((size_t)(t0 + s) * BB + b) * NN + n;
                out_spk[o] = sp ? 1.0f : 0.0f;
                out_v[o]   = vo;
            }
        }
        if (act)
            ((unsigned char*)&g_spk[kwin % 3][n])[qb] = (unsigned char)mybits;

        // ---- grid-wide barrier (all NBLKS CTAs resident) ----
        if (kwin < NWIN - 1) {
            __syncthreads();
            if (tid == 0) {
                __threadfence();
                u32 a = atomicAdd(&g_bar_cnt, 1u);
                if (a == NBLKS - 1) {
                    atomicExch(&g_bar_cnt, 0u);
                    __threadfence();
                    atomicExch(&g_bar_gen, (u32)(kwin + 1));
                } else {
                    while (atomicAdd(&g_bar_gen, 0u) < (u32)(kwin + 1))
                        __nanosleep(64);
                    __threadfence();
                }
            }
            __syncthreads();
        }
    }
}

extern "C" void kernel_launch(void* const* d_in, const int* in_sizes, int n_in,
                              void* d_out, int out_size)
{
    const float* ext = (const float*)d_in[0];
    const float* w   = (const float*)d_in[1];
    const int*   idx = (const int*)d_in[2];

    float* out     = (float*)d_out;
    float* out_spk = out;
    float* out_v   = out + (size_t)TT * BB * NN;

    float decay = (float)exp(-0.005);

    cudaFuncSetAttribute(sim_all, cudaFuncAttributeMaxDynamicSharedMemorySize,
                         SMEM_BYTES);

    prep_all<<<NN / 8, 256>>>(idx, w);
    sim_all<<<NBLKS, THREADS, SMEM_BYTES>>>(ext, out_spk, out_v, decay);
}